// round 6
// baseline (speedup 1.0000x reference)
#include <cuda_runtime.h>

// RBF_random: out[b][o] = (1-d)^6 * (35 d^2 + 18 d + 3)/3 * w[o],
//   d = ||x[b] - c[o]||,  B=131072, OUT=512, IN=3.
// Issue-volume-bound. Diff-form d^2 (exact >=0, no clamps), smem pre-paired
// u64 loads (no pack MOVs), u64 streaming stores (no unpack), full-unroll
// immediate addressing (no per-row ALU). 2 outputs/thread, 256 threads.

typedef unsigned long long u64;

#define ROWS    16
#define THREADS 256          // OUT/2 = 512/2

__device__ __forceinline__ u64 pack2(float lo, float hi) {
    u64 r; asm("mov.b64 %0, {%1, %2};" : "=l"(r) : "f"(lo), "f"(hi)); return r;
}
__device__ __forceinline__ void unpack2(u64 v, float& lo, float& hi) {
    asm("mov.b64 {%0, %1}, %2;" : "=f"(lo), "=f"(hi) : "l"(v));
}
__device__ __forceinline__ u64 add2(u64 a, u64 b) {
    u64 d; asm("add.rn.f32x2 %0, %1, %2;" : "=l"(d) : "l"(a), "l"(b)); return d;
}
__device__ __forceinline__ u64 mul2(u64 a, u64 b) {
    u64 d; asm("mul.rn.f32x2 %0, %1, %2;" : "=l"(d) : "l"(a), "l"(b)); return d;
}
__device__ __forceinline__ u64 fma2(u64 a, u64 b, u64 c) {
    u64 d; asm("fma.rn.f32x2 %0, %1, %2, %3;" : "=l"(d) : "l"(a), "l"(b), "l"(c)); return d;
}
__device__ __forceinline__ float sqrt_ap(float x) {
    float r; asm("sqrt.approx.f32 %0, %1;" : "=f"(r) : "f"(x)); return r;
}
__device__ __forceinline__ void stg_cs_u64(float* p, u64 v) {
    asm volatile("st.global.cs.b64 [%0], %1;" :: "l"(p), "l"(v) : "memory");
}

__global__ void __launch_bounds__(THREADS, 6)
rbf_kernel(const float* __restrict__ x,
           const float* __restrict__ centers,
           const float* __restrict__ weights,
           float* __restrict__ out,
           int B)
{
    // Per row (32B): {xx,xx, xy,xy, xz,xz, xz,xz} as 4 u64 pairs.
    __shared__ u64 sx[ROWS * 4];

    const int tid = threadIdx.x;
    const int o0  = tid * 2;   // 2 consecutive output columns per thread
    const int b0  = blockIdx.x * ROWS;
    const int nrows = min(ROWS, B - b0);

    // Stage x rows as pre-duplicated pairs: thread t (t < nrows) -> row t.
    if (tid < nrows) {
        const float xx = x[(b0 + tid) * 3 + 0];
        const float xy = x[(b0 + tid) * 3 + 1];
        const float xz = x[(b0 + tid) * 3 + 2];
        u64* s = &sx[tid * 4];
        s[0] = pack2(xx, xx);
        s[1] = pack2(xy, xy);
        s[2] = pack2(xz, xz);
        s[3] = pack2(xz, xz);   // pad (keeps rows 32B-aligned)
    }

    // Per-thread constants (one f32x2 pair each): -c and w-folded poly coeffs.
    float ncx[2], ncy[2], ncz[2], w35[2], w6[2], w1[2];
#pragma unroll
    for (int i = 0; i < 2; i++) {
        ncx[i] = -centers[(o0 + i) * 3 + 0];
        ncy[i] = -centers[(o0 + i) * 3 + 1];
        ncz[i] = -centers[(o0 + i) * 3 + 2];
        const float w = weights[o0 + i];
        w35[i] = w * (35.0f / 3.0f);
        w6[i]  = w * 6.0f;
        w1[i]  = w;
    }
    const u64 NCX = pack2(ncx[0], ncx[1]);
    const u64 NCY = pack2(ncy[0], ncy[1]);
    const u64 NCZ = pack2(ncz[0], ncz[1]);
    const u64 P2W = pack2(w35[0], w35[1]);
    const u64 P1W = pack2(w6[0],  w6[1]);
    const u64 P0W = pack2(w1[0],  w1[1]);
    const u64 KM1 = pack2(-1.0f, -1.0f);   // t = d - 1; (d-1)^6 == (1-d)^6

    __syncthreads();

    float* const obase = out + (size_t)b0 * 512 + o0;

    if (nrows == ROWS) {
#pragma unroll
        for (int r = 0; r < ROWS; r++) {
            // Direct u64 loads: no pack MOVs (LDS.128 + LDS.64, imm offsets).
            const ulonglong2 pxy = *reinterpret_cast<const ulonglong2*>(&sx[r * 4]);
            const u64 PZ = sx[r * 4 + 2];

            u64 dx = add2(pxy.x, NCX);
            u64 dy = add2(pxy.y, NCY);
            u64 dz = add2(PZ,    NCZ);
            u64 d2 = mul2(dx, dx);
            d2 = fma2(dy, dy, d2);
            d2 = fma2(dz, dz, d2);                    // exact >= 0
            float a, b; unpack2(d2, a, b);
            u64 d  = pack2(sqrt_ap(a), sqrt_ap(b));
            u64 t  = add2(d, KM1);                    // d - 1
            u64 t2 = mul2(t, t), t3 = mul2(t2, t), t6 = mul2(t3, t3);
            u64 p  = fma2(d, P1W, P0W);
            p      = fma2(d2, P2W, p);                // (35w/3)d^2 + 6w d + w
            stg_cs_u64(obase + (size_t)r * 512, mul2(t6, p));   // STG.64.CS
        }
    } else {
        for (int r = 0; r < nrows; r++) {
            const ulonglong2 pxy = *reinterpret_cast<const ulonglong2*>(&sx[r * 4]);
            const u64 PZ = sx[r * 4 + 2];
            u64 dx = add2(pxy.x, NCX);
            u64 dy = add2(pxy.y, NCY);
            u64 dz = add2(PZ,    NCZ);
            u64 d2 = mul2(dx, dx);
            d2 = fma2(dy, dy, d2);
            d2 = fma2(dz, dz, d2);
            float a, b; unpack2(d2, a, b);
            u64 d  = pack2(sqrt_ap(a), sqrt_ap(b));
            u64 t  = add2(d, KM1);
            u64 t2 = mul2(t, t), t3 = mul2(t2, t), t6 = mul2(t3, t3);
            u64 p  = fma2(d, P1W, P0W);
            p      = fma2(d2, P2W, p);
            stg_cs_u64(obase + (size_t)r * 512, mul2(t6, p));
        }
    }
}

extern "C" void kernel_launch(void* const* d_in, const int* in_sizes, int n_in,
                              void* d_out, int out_size)
{
    const float* x       = (const float*)d_in[0];  // (B, 3)
    const float* centers = (const float*)d_in[1];  // (512, 3)
    const float* weights = (const float*)d_in[2];  // (512,)
    float* out           = (float*)d_out;          // (B, 512)

    const int B = in_sizes[0] / 3;
    const int grid = (B + ROWS - 1) / ROWS;
    rbf_kernel<<<grid, THREADS>>>(x, centers, weights, out, B);
}

// round 7
// speedup vs baseline: 1.0494x; 1.0494x over previous
#include <cuda_runtime.h>

// RBF_random: out[b][o] = (1-d)^6 * (35 d^2 + 18 d + 3)/3 * w[o],
//   d = ||x[b] - c[o]||,  B=131072, OUT=512, IN=3.
// At the LTS write-path ceiling (~6.9 TB/s): widest stores (STG.128.CS,
// 4 outputs/thread) + leanest body (diff-form d^2, clamp-free sqrt, u64
// pre-paired smem, immediate addressing). 128 thr, ROWS=16, grid=8192.

typedef unsigned long long u64;

#define ROWS    16
#define THREADS 128          // OUT/4 = 512/4

__device__ __forceinline__ u64 pack2(float lo, float hi) {
    u64 r; asm("mov.b64 %0, {%1, %2};" : "=l"(r) : "f"(lo), "f"(hi)); return r;
}
__device__ __forceinline__ void unpack2(u64 v, float& lo, float& hi) {
    asm("mov.b64 {%0, %1}, %2;" : "=f"(lo), "=f"(hi) : "l"(v));
}
__device__ __forceinline__ u64 add2(u64 a, u64 b) {
    u64 d; asm("add.rn.f32x2 %0, %1, %2;" : "=l"(d) : "l"(a), "l"(b)); return d;
}
__device__ __forceinline__ u64 mul2(u64 a, u64 b) {
    u64 d; asm("mul.rn.f32x2 %0, %1, %2;" : "=l"(d) : "l"(a), "l"(b)); return d;
}
__device__ __forceinline__ u64 fma2(u64 a, u64 b, u64 c) {
    u64 d; asm("fma.rn.f32x2 %0, %1, %2, %3;" : "=l"(d) : "l"(a), "l"(b), "l"(c)); return d;
}
__device__ __forceinline__ float sqrt_ap(float x) {
    float r; asm("sqrt.approx.f32 %0, %1;" : "=f"(r) : "f"(x)); return r;
}
__device__ __forceinline__ void stg_cs_v4(float* p, float a, float b, float c, float d) {
    asm volatile("st.global.cs.v4.f32 [%0], {%1, %2, %3, %4};"
                 :: "l"(p), "f"(a), "f"(b), "f"(c), "f"(d) : "memory");
}

__global__ void __launch_bounds__(THREADS, 8)
rbf_kernel(const float* __restrict__ x,
           const float* __restrict__ centers,
           const float* __restrict__ weights,
           float* __restrict__ out,
           int B)
{
    // Per row (32B): {xx,xx, xy,xy, xz,xz, pad} as 4 u64 pairs.
    __shared__ u64 sx[ROWS * 4];

    const int tid = threadIdx.x;
    const int o0  = tid * 4;   // 4 consecutive output columns per thread
    const int b0  = blockIdx.x * ROWS;
    const int nrows = min(ROWS, B - b0);

    // Stage x rows as pre-duplicated pairs: thread t (t < nrows) -> row t.
    if (tid < nrows) {
        const float xx = x[(b0 + tid) * 3 + 0];
        const float xy = x[(b0 + tid) * 3 + 1];
        const float xz = x[(b0 + tid) * 3 + 2];
        u64* s = &sx[tid * 4];
        s[0] = pack2(xx, xx);
        s[1] = pack2(xy, xy);
        s[2] = pack2(xz, xz);
        s[3] = pack2(xz, xz);   // pad (32B row alignment)
    }

    // Per-thread constants: -c (diff form, exact d^2 >= 0) and w-folded coeffs.
    float ncx[4], ncy[4], ncz[4], w35[4], w6[4], w1[4];
#pragma unroll
    for (int i = 0; i < 4; i++) {
        ncx[i] = -centers[(o0 + i) * 3 + 0];
        ncy[i] = -centers[(o0 + i) * 3 + 1];
        ncz[i] = -centers[(o0 + i) * 3 + 2];
        const float w = weights[o0 + i];
        w35[i] = w * (35.0f / 3.0f);
        w6[i]  = w * 6.0f;
        w1[i]  = w;
    }
    const u64 NCX0 = pack2(ncx[0], ncx[1]), NCX1 = pack2(ncx[2], ncx[3]);
    const u64 NCY0 = pack2(ncy[0], ncy[1]), NCY1 = pack2(ncy[2], ncy[3]);
    const u64 NCZ0 = pack2(ncz[0], ncz[1]), NCZ1 = pack2(ncz[2], ncz[3]);
    const u64 P2W0 = pack2(w35[0], w35[1]), P2W1 = pack2(w35[2], w35[3]);
    const u64 P1W0 = pack2(w6[0],  w6[1]),  P1W1 = pack2(w6[2],  w6[3]);
    const u64 P0W0 = pack2(w1[0],  w1[1]),  P0W1 = pack2(w1[2],  w1[3]);
    const u64 KM1  = pack2(-1.0f, -1.0f);   // t = d - 1; (d-1)^6 == (1-d)^6

    __syncthreads();

    float* const obase = out + (size_t)b0 * 512 + o0;

    if (nrows == ROWS) {
#pragma unroll
        for (int r = 0; r < ROWS; r++) {
            const ulonglong2 pxy = *reinterpret_cast<const ulonglong2*>(&sx[r * 4]);
            const u64 PZ = sx[r * 4 + 2];

            u64 res0, res1;
            {   // outputs o0, o0+1
                u64 dx = add2(pxy.x, NCX0), dy = add2(pxy.y, NCY0), dz = add2(PZ, NCZ0);
                u64 d2 = mul2(dx, dx); d2 = fma2(dy, dy, d2); d2 = fma2(dz, dz, d2);
                float a, b; unpack2(d2, a, b);
                u64 d  = pack2(sqrt_ap(a), sqrt_ap(b));
                u64 t  = add2(d, KM1);
                u64 t2 = mul2(t, t), t3 = mul2(t2, t), t6 = mul2(t3, t3);
                u64 p  = fma2(d, P1W0, P0W0);
                p      = fma2(d2, P2W0, p);
                res0   = mul2(t6, p);
            }
            {   // outputs o0+2, o0+3
                u64 dx = add2(pxy.x, NCX1), dy = add2(pxy.y, NCY1), dz = add2(PZ, NCZ1);
                u64 d2 = mul2(dx, dx); d2 = fma2(dy, dy, d2); d2 = fma2(dz, dz, d2);
                float a, b; unpack2(d2, a, b);
                u64 d  = pack2(sqrt_ap(a), sqrt_ap(b));
                u64 t  = add2(d, KM1);
                u64 t2 = mul2(t, t), t3 = mul2(t2, t), t6 = mul2(t3, t3);
                u64 p  = fma2(d, P1W1, P0W1);
                p      = fma2(d2, P2W1, p);
                res1   = mul2(t6, p);
            }

            float a0, a1, a2, a3;
            unpack2(res0, a0, a1);
            unpack2(res1, a2, a3);
            stg_cs_v4(obase + (size_t)r * 512, a0, a1, a2, a3);   // STG.128.CS
        }
    } else {
        for (int r = 0; r < nrows; r++) {
            const ulonglong2 pxy = *reinterpret_cast<const ulonglong2*>(&sx[r * 4]);
            const u64 PZ = sx[r * 4 + 2];
            u64 res0, res1;
            {
                u64 dx = add2(pxy.x, NCX0), dy = add2(pxy.y, NCY0), dz = add2(PZ, NCZ0);
                u64 d2 = mul2(dx, dx); d2 = fma2(dy, dy, d2); d2 = fma2(dz, dz, d2);
                float a, b; unpack2(d2, a, b);
                u64 d  = pack2(sqrt_ap(a), sqrt_ap(b));
                u64 t  = add2(d, KM1);
                u64 t2 = mul2(t, t), t3 = mul2(t2, t), t6 = mul2(t3, t3);
                u64 p  = fma2(d, P1W0, P0W0);
                p      = fma2(d2, P2W0, p);
                res0   = mul2(t6, p);
            }
            {
                u64 dx = add2(pxy.x, NCX1), dy = add2(pxy.y, NCY1), dz = add2(PZ, NCZ1);
                u64 d2 = mul2(dx, dx); d2 = fma2(dy, dy, d2); d2 = fma2(dz, dz, d2);
                float a, b; unpack2(d2, a, b);
                u64 d  = pack2(sqrt_ap(a), sqrt_ap(b));
                u64 t  = add2(d, KM1);
                u64 t2 = mul2(t, t), t3 = mul2(t2, t), t6 = mul2(t3, t3);
                u64 p  = fma2(d, P1W1, P0W1);
                p      = fma2(d2, P2W1, p);
                res1   = mul2(t6, p);
            }
            float a0, a1, a2, a3;
            unpack2(res0, a0, a1);
            unpack2(res1, a2, a3);
            stg_cs_v4(obase + (size_t)r * 512, a0, a1, a2, a3);
        }
    }
}

extern "C" void kernel_launch(void* const* d_in, const int* in_sizes, int n_in,
                              void* d_out, int out_size)
{
    const float* x       = (const float*)d_in[0];  // (B, 3)
    const float* centers = (const float*)d_in[1];  // (512, 3)
    const float* weights = (const float*)d_in[2];  // (512,)
    float* out           = (float*)d_out;          // (B, 512)

    const int B = in_sizes[0] / 3;
    const int grid = (B + ROWS - 1) / ROWS;
    rbf_kernel<<<grid, THREADS>>>(x, centers, weights, out, B);
}

// round 8
// speedup vs baseline: 1.0601x; 1.0101x over previous
#include <cuda_runtime.h>

// RBF_random: out[b][o] = (1-d)^6 * (35 d^2 + 18 d + 3)/3 * w[o],
//   d = ||x[b] - c[o]||,  B=131072, OUT=512, IN=3.
// Store-stream bound (268 MB, STG.128.CS). Compute squeezed under the write
// floor: dot-form d^2 = (x^2+c^2) - 2x.c (4 fma-pipe ops/pair; safety clamp
// is FMNMX on the ALU pipe), w folded into poly coeffs, u64 pre-paired smem
// (2x LDS.128/row), immediate addressing. 128 thr, ROWS=16, grid=8192.

typedef unsigned long long u64;

#define ROWS    16
#define THREADS 128          // OUT/4 = 512/4

__device__ __forceinline__ u64 pack2(float lo, float hi) {
    u64 r; asm("mov.b64 %0, {%1, %2};" : "=l"(r) : "f"(lo), "f"(hi)); return r;
}
__device__ __forceinline__ void unpack2(u64 v, float& lo, float& hi) {
    asm("mov.b64 {%0, %1}, %2;" : "=f"(lo), "=f"(hi) : "l"(v));
}
__device__ __forceinline__ u64 add2(u64 a, u64 b) {
    u64 d; asm("add.rn.f32x2 %0, %1, %2;" : "=l"(d) : "l"(a), "l"(b)); return d;
}
__device__ __forceinline__ u64 mul2(u64 a, u64 b) {
    u64 d; asm("mul.rn.f32x2 %0, %1, %2;" : "=l"(d) : "l"(a), "l"(b)); return d;
}
__device__ __forceinline__ u64 fma2(u64 a, u64 b, u64 c) {
    u64 d; asm("fma.rn.f32x2 %0, %1, %2, %3;" : "=l"(d) : "l"(a), "l"(b), "l"(c)); return d;
}
__device__ __forceinline__ float sqrt_ap(float x) {
    float r; asm("sqrt.approx.f32 %0, %1;" : "=f"(r) : "f"(x)); return r;
}
__device__ __forceinline__ void stg_cs_v4(float* p, float a, float b, float c, float d) {
    asm volatile("st.global.cs.v4.f32 [%0], {%1, %2, %3, %4};"
                 :: "l"(p), "f"(a), "f"(b), "f"(c), "f"(d) : "memory");
}

__global__ void __launch_bounds__(THREADS, 8)
rbf_kernel(const float* __restrict__ x,
           const float* __restrict__ centers,
           const float* __restrict__ weights,
           float* __restrict__ out,
           int B)
{
    // Per row (32B): {xx,xx, xy,xy, xz,xz, x2,x2} as 4 u64 pairs -> 2x LDS.128.
    __shared__ u64 sx[ROWS * 4];

    const int tid = threadIdx.x;
    const int o0  = tid * 4;   // 4 consecutive output columns per thread
    const int b0  = blockIdx.x * ROWS;
    const int nrows = min(ROWS, B - b0);

    // Stage x rows as pre-duplicated pairs (x^2 computed once per row here).
    if (tid < nrows) {
        const float xx = x[(b0 + tid) * 3 + 0];
        const float xy = x[(b0 + tid) * 3 + 1];
        const float xz = x[(b0 + tid) * 3 + 2];
        const float x2 = xx * xx + xy * xy + xz * xz;
        u64* s = &sx[tid * 4];
        s[0] = pack2(xx, xx);
        s[1] = pack2(xy, xy);
        s[2] = pack2(xz, xz);
        s[3] = pack2(x2, x2);
    }

    // Per-thread constants: -2c, |c|^2, w-folded poly coeffs.
    float m2x[4], m2y[4], m2z[4], c2[4], w35[4], w6[4], w1[4];
#pragma unroll
    for (int i = 0; i < 4; i++) {
        const float a = centers[(o0 + i) * 3 + 0];
        const float b = centers[(o0 + i) * 3 + 1];
        const float c = centers[(o0 + i) * 3 + 2];
        m2x[i] = -2.0f * a; m2y[i] = -2.0f * b; m2z[i] = -2.0f * c;
        c2[i]  = a * a + b * b + c * c;
        const float w = weights[o0 + i];
        w35[i] = w * (35.0f / 3.0f);
        w6[i]  = w * 6.0f;
        w1[i]  = w;
    }
    const u64 M2X0 = pack2(m2x[0], m2x[1]), M2X1 = pack2(m2x[2], m2x[3]);
    const u64 M2Y0 = pack2(m2y[0], m2y[1]), M2Y1 = pack2(m2y[2], m2y[3]);
    const u64 M2Z0 = pack2(m2z[0], m2z[1]), M2Z1 = pack2(m2z[2], m2z[3]);
    const u64 C20  = pack2(c2[0],  c2[1]),  C21  = pack2(c2[2],  c2[3]);
    const u64 P2W0 = pack2(w35[0], w35[1]), P2W1 = pack2(w35[2], w35[3]);
    const u64 P1W0 = pack2(w6[0],  w6[1]),  P1W1 = pack2(w6[2],  w6[3]);
    const u64 P0W0 = pack2(w1[0],  w1[1]),  P0W1 = pack2(w1[2],  w1[3]);
    const u64 KM1  = pack2(-1.0f, -1.0f);   // t = d - 1; (d-1)^6 == (1-d)^6

    __syncthreads();

    float* const obase = out + (size_t)b0 * 512 + o0;

#pragma unroll
    for (int r = 0; r < ROWS; r++) {
        if (r >= nrows) break;
        const ulonglong2 pxy = *reinterpret_cast<const ulonglong2*>(&sx[r * 4]);
        const ulonglong2 pzq = *reinterpret_cast<const ulonglong2*>(&sx[r * 4 + 2]);
        const u64 PX = pxy.x, PY = pxy.y, PZ = pzq.x, PX2 = pzq.y;

        u64 res0, res1;
        {   // outputs o0, o0+1
            u64 d2 = add2(C20, PX2);                  // x^2 + c^2
            d2 = fma2(M2Z0, PZ, d2);
            d2 = fma2(M2Y0, PY, d2);
            d2 = fma2(M2X0, PX, d2);                  // - 2 x.c
            float a, b; unpack2(d2, a, b);
            u64 d  = pack2(sqrt_ap(fmaxf(a, 0.0f)), sqrt_ap(fmaxf(b, 0.0f)));
            u64 t  = add2(d, KM1);                    // d - 1
            u64 t2 = mul2(t, t), t3 = mul2(t2, t), t6 = mul2(t3, t3);
            u64 p  = fma2(d, P1W0, P0W0);
            p      = fma2(d2, P2W0, p);               // (35w/3)d^2 + 6w d + w
            res0   = mul2(t6, p);
        }
        {   // outputs o0+2, o0+3
            u64 d2 = add2(C21, PX2);
            d2 = fma2(M2Z1, PZ, d2);
            d2 = fma2(M2Y1, PY, d2);
            d2 = fma2(M2X1, PX, d2);
            float a, b; unpack2(d2, a, b);
            u64 d  = pack2(sqrt_ap(fmaxf(a, 0.0f)), sqrt_ap(fmaxf(b, 0.0f)));
            u64 t  = add2(d, KM1);
            u64 t2 = mul2(t, t), t3 = mul2(t2, t), t6 = mul2(t3, t3);
            u64 p  = fma2(d, P1W1, P0W1);
            p      = fma2(d2, P2W1, p);
            res1   = mul2(t6, p);
        }

        float a0, a1, a2, a3;
        unpack2(res0, a0, a1);
        unpack2(res1, a2, a3);
        stg_cs_v4(obase + (size_t)r * 512, a0, a1, a2, a3);   // STG.128.CS
    }
}

extern "C" void kernel_launch(void* const* d_in, const int* in_sizes, int n_in,
                              void* d_out, int out_size)
{
    const float* x       = (const float*)d_in[0];  // (B, 3)
    const float* centers = (const float*)d_in[1];  // (512, 3)
    const float* weights = (const float*)d_in[2];  // (512,)
    float* out           = (float*)d_out;          // (B, 512)

    const int B = in_sizes[0] / 3;
    const int grid = (B + ROWS - 1) / ROWS;
    rbf_kernel<<<grid, THREADS>>>(x, centers, weights, out, B);
}